// round 2
// baseline (speedup 1.0000x reference)
#include <cuda_runtime.h>
#include <cub/cub.cuh>

#define NB     16
#define NCLS   20
#define NPM    27280          // anchors per modality
#define NPB    (2*NPM)        // 54560 anchors per batch
#define TOTAL  (NB*NPB)       // 872960
#define MAXD   1000
#define MASKW  16             // 1000 bits -> 16 u64 words
#define TOPN   (NB*MAXD)      // 16000

struct Ptrs { const float* p[30]; };

// ---- static device scratch (no allocations allowed) ----
__device__ __align__(16)  unsigned long long g_keys[TOTAL];
__device__ __align__(16)  unsigned long long g_keys_sorted[TOTAL];
__device__ __align__(256) unsigned char      g_cub_temp[16*1024*1024];
__device__ float              g_top_s[TOPN];
__device__ int                g_top_c[TOPN];
__device__ float              g_top_b[TOPN*4];
__device__ unsigned char      g_valid[TOPN];
__device__ unsigned char      g_keep[TOPN];
__device__ float              g_maxc[NB];
__device__ float              g_ob[TOPN*4];
__device__ float              g_area[TOPN];
__device__ unsigned long long g_mask[(size_t)TOPN*MASKW];

// sigmoid exactly as XLA logistic expansion: 1/(1+exp(-x)), no FMA contraction
__device__ __forceinline__ float sigm(float x){
    return __fdiv_rn(1.0f, __fadd_rn(1.0f, expf(-x)));
}

__device__ __forceinline__ void locate(int m, int& lvl, int& pos, int& w, int& st, int& hw){
    if (m < 20480)      { lvl=0; pos=m;        w=160; st=8;   hw=20480; }
    else if (m < 25600) { lvl=1; pos=m-20480;  w=80;  st=16;  hw=5120;  }
    else if (m < 26880) { lvl=2; pos=m-25600;  w=40;  st=32;  hw=1280;  }
    else if (m < 27200) { lvl=3; pos=m-26880;  w=20;  st=64;  hw=320;   }
    else                { lvl=4; pos=m-27200;  w=10;  st=128; hw=80;    }
}

// ---- 1. decode: score per (b, anchor) -> 64-bit sort key ----
__global__ __launch_bounds__(256) void k_decode(Ptrs P, unsigned long long* __restrict__ keys){
    int n = blockIdx.x*blockDim.x + threadIdx.x;
    if (n >= NPB) return;
    int b   = blockIdx.y;
    int mod = (n >= NPM) ? 1 : 0;
    int m   = n - mod*NPM;
    int lvl,pos,w,st,hw; locate(m,lvl,pos,w,st,hw);
    const float* __restrict__ cls = P.p[mod*15 + lvl];
    const float* __restrict__ cnt = P.p[mod*15 + 5 + lvl];
    int cbase = b*NCLS*hw + pos;
    float pmax = sigm(cls[cbase]);
    #pragma unroll
    for (int c=1;c<NCLS;c++) pmax = fmaxf(pmax, sigm(cls[cbase + c*hw]));
    float q = sigm(cnt[b*hw + pos]);
    float score = __fsqrt_rn(__fmul_rn(pmax, q));
    // key: [63:60]=batch | [59:28]=ordered score bits | [27:0]=inverted index (stable ties)
    unsigned long long key = ((unsigned long long)b << 60)
        | ((unsigned long long)(__float_as_uint(score) | 0x80000000u) << 28)
        | (unsigned long long)(0x0FFFFFFFu - (unsigned)n);
    keys[b*NPB + n] = key;
}

// ---- 3. gather top-1000 per batch, recompute class/box for selected anchors ----
__global__ void k_gather(Ptrs P, const unsigned long long* __restrict__ sk){
    int t = blockIdx.x*blockDim.x + threadIdx.x;
    if (t >= TOPN) return;
    int b = t / MAXD, j = t - b*MAXD;
    // descending sort => batch (NB-1-b) segment comes first
    unsigned long long key = sk[(size_t)(NB-1-b)*NPB + j];
    unsigned int so = (unsigned int)(key >> 28);
    float score = __uint_as_float(so & 0x7FFFFFFFu);
    int n = 0x0FFFFFFF - (int)(key & 0x0FFFFFFFull);
    int mod = (n >= NPM) ? 1 : 0;
    int m = n - mod*NPM;
    int lvl,pos,w,st,hw; locate(m,lvl,pos,w,st,hw);
    const float* cls = P.p[mod*15 + lvl];
    const float* reg = P.p[mod*15 + 10 + lvl];
    int cbase = b*NCLS*hw + pos;
    float best = sigm(cls[cbase]); int bi = 0;
    #pragma unroll
    for (int c=1;c<NCLS;c++){ float s = sigm(cls[cbase + c*hw]); if (s > best){best=s;bi=c;} }
    int y = pos / w, x = pos - y*w;
    float fx = (float)(x*st + (st>>1));
    float fy = (float)(y*st + (st>>1));
    int rbase = b*4*hw + pos;
    float r0=reg[rbase], r1=reg[rbase+hw], r2=reg[rbase+2*hw], r3=reg[rbase+3*hw];
    g_top_s[t] = score;
    g_top_c[t] = bi + 1;
    g_top_b[4*t+0] = __fsub_rn(fx, r0);
    g_top_b[4*t+1] = __fsub_rn(fy, r1);
    g_top_b[4*t+2] = __fadd_rn(fx, r2);
    g_top_b[4*t+3] = __fadd_rn(fy, r3);
    g_valid[t] = (score >= 0.05f) ? 1 : 0;
}

// ---- 4. per-batch maxc = max(where(valid, boxes, 0)) ----
__global__ void k_maxc(){
    int b = blockIdx.x;
    __shared__ float red[256];
    float mx = -INFINITY;
    for (int j = threadIdx.x; j < MAXD; j += 256){
        int t = b*MAXD + j;
        if (g_valid[t]){
            const float* bx = &g_top_b[4*t];
            mx = fmaxf(mx, fmaxf(fmaxf(bx[0],bx[1]), fmaxf(bx[2],bx[3])));
        } else {
            mx = fmaxf(mx, 0.0f);
        }
    }
    red[threadIdx.x] = mx; __syncthreads();
    for (int s=128; s>0; s>>=1){
        if (threadIdx.x < s) red[threadIdx.x] = fmaxf(red[threadIdx.x], red[threadIdx.x+s]);
        __syncthreads();
    }
    if (threadIdx.x==0) g_maxc[b] = red[0];
}

// ---- 5. class-offset boxes + areas ----
__global__ void k_offset(){
    int t = blockIdx.x*blockDim.x + threadIdx.x;
    if (t >= TOPN) return;
    int b = t / MAXD;
    float off = __fmul_rn((float)g_top_c[t], __fadd_rn(g_maxc[b], 1.0f));
    float x1 = __fadd_rn(g_top_b[4*t+0], off);
    float y1 = __fadd_rn(g_top_b[4*t+1], off);
    float x2 = __fadd_rn(g_top_b[4*t+2], off);
    float y2 = __fadd_rn(g_top_b[4*t+3], off);
    g_ob[4*t+0]=x1; g_ob[4*t+1]=y1; g_ob[4*t+2]=x2; g_ob[4*t+3]=y2;
    g_area[t] = __fmul_rn(__fadd_rn(__fsub_rn(x2,x1),1.0f),
                          __fadd_rn(__fsub_rn(y2,y1),1.0f));
}

// ---- 6. IoU > 0.6 suppression bitmask (per batch: 1000 rows x 16 u64 words) ----
__global__ __launch_bounds__(64) void k_mask(){
    int b  = blockIdx.z;
    int i  = blockIdx.x*64 + threadIdx.x;
    int j0 = blockIdx.y*64;
    __shared__ float sx1[64],sy1[64],sx2[64],sy2[64],sa[64];
    int jj = j0 + threadIdx.x;
    if (jj < MAXD){
        int tj = b*MAXD + jj;
        sx1[threadIdx.x]=g_ob[4*tj];   sy1[threadIdx.x]=g_ob[4*tj+1];
        sx2[threadIdx.x]=g_ob[4*tj+2]; sy2[threadIdx.x]=g_ob[4*tj+3];
        sa[threadIdx.x]=g_area[tj];
    }
    __syncthreads();
    if (i >= MAXD) return;
    int ti = b*MAXD + i;
    float x1=g_ob[4*ti], y1=g_ob[4*ti+1], x2=g_ob[4*ti+2], y2=g_ob[4*ti+3], ai=g_area[ti];
    unsigned long long word = 0;
    int jn = min(64, MAXD - j0);
    for (int k=0;k<jn;k++){
        float xx1=fmaxf(x1,sx1[k]), yy1=fmaxf(y1,sy1[k]);
        float xx2=fminf(x2,sx2[k]), yy2=fminf(y2,sy2[k]);
        float iw=fmaxf(__fadd_rn(__fsub_rn(xx2,xx1),1.0f),0.0f);
        float ih=fmaxf(__fadd_rn(__fsub_rn(yy2,yy1),1.0f),0.0f);
        float inter=__fmul_rn(iw,ih);
        float iou=__fdiv_rn(inter, __fsub_rn(__fadd_rn(ai,sa[k]),inter));
        if (iou > 0.6f) word |= (1ull<<k);
    }
    g_mask[(size_t)ti*MASKW + blockIdx.y] = word;
}

// ---- 7. sequential greedy scan (order == identity), 1 warp per batch ----
__global__ void k_scan(){
    int b = blockIdx.x;
    int lane = threadIdx.x;
    unsigned long long removed = 0;  // lanes 0..15 hold the 16 suppression words
    const unsigned long long* mrow = &g_mask[(size_t)b*MAXD*MASKW];
    for (int i=0;i<MAXD;i++){
        unsigned long long rw = __shfl_sync(0xffffffffu, removed, i>>6);
        bool k = g_valid[b*MAXD+i] && !((rw >> (i&63)) & 1ull);
        if (lane==0) g_keep[b*MAXD+i] = k ? 1 : 0;
        if (k && lane < MASKW) removed |= mrow[(size_t)i*MASKW + lane];
    }
}

// ---- 8. clip + mask + write all four outputs (f32, concatenated) ----
__global__ void k_out(float* __restrict__ out){
    int t = blockIdx.x*blockDim.x + threadIdx.x;
    if (t >= TOPN) return;
    float kf = g_keep[t] ? 1.0f : 0.0f;
    out[t]        = __fmul_rn(g_top_s[t], kf);                        // scores
    out[TOPN + t] = g_keep[t] ? (float)g_top_c[t] : 0.0f;             // classes
    float x1 = fminf(fmaxf(g_top_b[4*t+0],0.0f),1279.0f);
    float y1 = fminf(fmaxf(g_top_b[4*t+1],0.0f),1023.0f);
    float x2 = fminf(fmaxf(g_top_b[4*t+2],0.0f),1279.0f);
    float y2 = fminf(fmaxf(g_top_b[4*t+3],0.0f),1023.0f);
    out[2*TOPN + 4*t+0]=__fmul_rn(x1,kf);                             // boxes
    out[2*TOPN + 4*t+1]=__fmul_rn(y1,kf);
    out[2*TOPN + 4*t+2]=__fmul_rn(x2,kf);
    out[2*TOPN + 4*t+3]=__fmul_rn(y2,kf);
    out[6*TOPN + t]=kf;                                               // keep
}

extern "C" void kernel_launch(void* const* d_in, const int* in_sizes, int n_in,
                              void* d_out, int out_size){
    Ptrs P;
    for (int i=0;i<30;i++) P.p[i] = (const float*)d_in[i];

    unsigned long long *keys=nullptr, *ksorted=nullptr; void* temp=nullptr;
    cudaGetSymbolAddress((void**)&keys,    g_keys);
    cudaGetSymbolAddress((void**)&ksorted, g_keys_sorted);
    cudaGetSymbolAddress(&temp,            g_cub_temp);

    dim3 gdec((NPB+255)/256, NB);
    k_decode<<<gdec,256>>>(P, keys);

    size_t tb = 0;
    cub::DeviceRadixSort::SortKeysDescending(nullptr, tb, keys, ksorted, TOTAL);
    if (tb > sizeof(g_cub_temp)) tb = sizeof(g_cub_temp);
    cub::DeviceRadixSort::SortKeysDescending(temp, tb, keys, ksorted, TOTAL);

    k_gather<<<(TOPN+255)/256,256>>>(P, ksorted);
    k_maxc<<<NB,256>>>();
    k_offset<<<(TOPN+127)/128,128>>>();
    k_mask<<<dim3((MAXD+63)/64, MASKW, NB),64>>>();
    k_scan<<<NB,32>>>();
    k_out<<<(TOPN+255)/256,256>>>((float*)d_out);
}

// round 3
// speedup vs baseline: 2.2727x; 2.2727x over previous
#include <cuda_runtime.h>

#define NB     16
#define NCLS   20
#define NPM    27280          // anchors per modality
#define NPB    (2*NPM)        // 54560 anchors per batch
#define TOTAL  (NB*NPB)       // 872960
#define MAXD   1000
#define NPAD   1024           // padded detections (16 x 64)
#define MASKW  16             // 1024 bits -> 16 u64 words
#define TOPN   (NB*MAXD)      // 16000
#define HBINS  8192
#define CAP    6144           // candidate capacity per batch

struct Ptrs { const float* p[30]; };

// ---- static device scratch (no allocations allowed) ----
__device__ unsigned int       g_scores[TOTAL];        // score float bits per (b,n)
__device__ int                g_hist[NB*HBINS];
__device__ int                g_thr[NB];
__device__ int                g_ccount[NB];
__device__ unsigned long long g_cand[NB*CAP];
__device__ unsigned long long g_topkeys[TOPN];
__device__ float              g_top_s[TOPN];
__device__ int                g_top_c[TOPN];
__device__ float              g_top_b[TOPN*4];
__device__ unsigned char      g_valid[TOPN];
__device__ float              g_maxc[NB];
__device__ float              g_ob[TOPN*4];
__device__ float              g_area[TOPN];
__device__ unsigned long long g_mask[(size_t)NB*NPAD*MASKW];
__device__ unsigned long long g_keepw[NB*MASKW];

// sigmoid exactly as round 1 (passed with rel_err 1.3e-8) — do not change
__device__ __forceinline__ float sigm(float x){
    return __fdiv_rn(1.0f, __fadd_rn(1.0f, expf(-x)));
}

__device__ __forceinline__ void locate(int m, int& lvl, int& pos, int& w, int& st, int& hw){
    if (m < 20480)      { lvl=0; pos=m;        w=160; st=8;   hw=20480; }
    else if (m < 25600) { lvl=1; pos=m-20480;  w=80;  st=16;  hw=5120;  }
    else if (m < 26880) { lvl=2; pos=m-25600;  w=40;  st=32;  hw=1280;  }
    else if (m < 27200) { lvl=3; pos=m-26880;  w=20;  st=64;  hw=320;   }
    else                { lvl=4; pos=m-27200;  w=10;  st=128; hw=80;    }
}

// ---- 1. decode scores + per-batch smem histogram ----
// max_c sigm(x_c) == sigm(max_c x_c) bit-exactly (monotone), so 2 expf/anchor.
__global__ __launch_bounds__(256) void k_decode(Ptrs P){
    __shared__ int sh[HBINS];
    int b = blockIdx.y;
    for (int i = threadIdx.x; i < HBINS; i += 256) sh[i] = 0;
    __syncthreads();
    int base = blockIdx.x * 2048;
    #pragma unroll
    for (int r = 0; r < 8; r++){
        int n = base + r*256 + threadIdx.x;
        if (n < NPB){
            int mod = (n >= NPM) ? 1 : 0;
            int m   = n - mod*NPM;
            int lvl,pos,w,st,hw; locate(m,lvl,pos,w,st,hw);
            const float* __restrict__ cls = P.p[mod*15 + lvl];
            const float* __restrict__ cnt = P.p[mod*15 + 5 + lvl];
            int cbase = b*NCLS*hw + pos;
            float lm = cls[cbase];
            #pragma unroll
            for (int c=1;c<NCLS;c++) lm = fmaxf(lm, cls[cbase + c*hw]);
            float pmax = sigm(lm);
            float q = sigm(cnt[b*hw + pos]);
            float score = __fsqrt_rn(__fmul_rn(pmax, q));
            unsigned int sb = __float_as_uint(score);
            g_scores[b*NPB + n] = sb;
            atomicAdd(&sh[sb >> 17], 1);
        }
    }
    __syncthreads();
    for (int i = threadIdx.x; i < HBINS; i += 256){
        int v = sh[i];
        if (v) atomicAdd(&g_hist[b*HBINS + i], v);
    }
}

// ---- 2. per-batch bin threshold so that count(bin >= T) >= 1000 ----
__global__ void k_thresh(){
    int b = blockIdx.x;
    __shared__ int gsum[256];
    const int* h = &g_hist[b*HBINS];
    int s = 0;
    #pragma unroll 8
    for (int k = 0; k < 32; k++) s += h[threadIdx.x*32 + k];
    gsum[threadIdx.x] = s;
    __syncthreads();
    if (threadIdx.x == 0){
        int acc = 0, g = 255;
        while (g > 0 && acc + gsum[g] < MAXD){ acc += gsum[g]; g--; }
        int T = g*32;
        for (int k = 31; k >= 0; k--){
            acc += h[g*32 + k];
            if (acc >= MAXD){ T = g*32 + k; break; }
        }
        g_thr[b] = T;
    }
}

// ---- 3. compact candidates (score bin >= threshold) ----
__global__ void k_compact(){
    int n = blockIdx.x*256 + threadIdx.x;
    if (n >= NPB) return;
    int b = blockIdx.y;
    unsigned int sb = g_scores[b*NPB + n];
    if ((int)(sb >> 17) >= g_thr[b]){
        int slot = atomicAdd(&g_ccount[b], 1);
        if (slot < CAP)
            g_cand[b*CAP + slot] =
                ((unsigned long long)sb << 28) | (unsigned long long)(0x0FFFFFFFu - (unsigned)n);
    }
}

// ---- 4. rank by enumeration -> sorted top-1000 keys (keys unique) ----
__global__ __launch_bounds__(256) void k_rank(){
    int b = blockIdx.y;
    int C = min(g_ccount[b], CAP);
    int idx = blockIdx.x*256 + threadIdx.x;
    unsigned long long my = (idx < C) ? g_cand[b*CAP + idx] : 0ull;
    int rank = 0;
    __shared__ unsigned long long tile[256];
    for (int t0 = 0; t0 < C; t0 += 256){
        int j = t0 + threadIdx.x;
        tile[threadIdx.x] = (j < C) ? g_cand[b*CAP + j] : 0ull;
        __syncthreads();
        int tn = min(256, C - t0);
        #pragma unroll 8
        for (int k = 0; k < tn; k++) rank += (tile[k] > my) ? 1 : 0;
        __syncthreads();
    }
    if (idx < C && rank < MAXD) g_topkeys[b*MAXD + rank] = my;
}

// ---- 5. gather: recompute class/box for the 1000 selected anchors ----
__global__ void k_gather(Ptrs P){
    int t = blockIdx.x*blockDim.x + threadIdx.x;
    if (t >= TOPN) return;
    int b = t / MAXD;
    unsigned long long key = g_topkeys[t];
    float score = __uint_as_float((unsigned int)(key >> 28));
    int n = 0x0FFFFFFF - (int)(key & 0x0FFFFFFFull);
    int mod = (n >= NPM) ? 1 : 0;
    int m = n - mod*NPM;
    int lvl,pos,w,st,hw; locate(m,lvl,pos,w,st,hw);
    const float* cls = P.p[mod*15 + lvl];
    const float* reg = P.p[mod*15 + 10 + lvl];
    int cbase = b*NCLS*hw + pos;
    // argmax in sigmoid space (first-occurrence semantics, exact vs reference)
    float best = sigm(cls[cbase]); int bi = 0;
    #pragma unroll
    for (int c=1;c<NCLS;c++){ float s = sigm(cls[cbase + c*hw]); if (s > best){best=s;bi=c;} }
    int y = pos / w, x = pos - y*w;
    float fx = (float)(x*st + (st>>1));
    float fy = (float)(y*st + (st>>1));
    int rbase = b*4*hw + pos;
    float r0=reg[rbase], r1=reg[rbase+hw], r2=reg[rbase+2*hw], r3=reg[rbase+3*hw];
    g_top_s[t] = score;
    g_top_c[t] = bi + 1;
    g_top_b[4*t+0] = __fsub_rn(fx, r0);
    g_top_b[4*t+1] = __fsub_rn(fy, r1);
    g_top_b[4*t+2] = __fadd_rn(fx, r2);
    g_top_b[4*t+3] = __fadd_rn(fy, r3);
    g_valid[t] = (score >= 0.05f) ? 1 : 0;
}

// ---- 6. per-batch maxc = max(where(valid, boxes, 0)) ----
__global__ void k_maxc(){
    int b = blockIdx.x;
    __shared__ float red[256];
    float mx = -INFINITY;
    for (int j = threadIdx.x; j < MAXD; j += 256){
        int t = b*MAXD + j;
        if (g_valid[t]){
            const float* bx = &g_top_b[4*t];
            mx = fmaxf(mx, fmaxf(fmaxf(bx[0],bx[1]), fmaxf(bx[2],bx[3])));
        } else {
            mx = fmaxf(mx, 0.0f);
        }
    }
    red[threadIdx.x] = mx; __syncthreads();
    for (int s=128; s>0; s>>=1){
        if (threadIdx.x < s) red[threadIdx.x] = fmaxf(red[threadIdx.x], red[threadIdx.x+s]);
        __syncthreads();
    }
    if (threadIdx.x==0) g_maxc[b] = red[0];
}

// ---- 7. class-offset boxes + areas ----
__global__ void k_offset(){
    int t = blockIdx.x*blockDim.x + threadIdx.x;
    if (t >= TOPN) return;
    int b = t / MAXD;
    float off = __fmul_rn((float)g_top_c[t], __fadd_rn(g_maxc[b], 1.0f));
    float x1 = __fadd_rn(g_top_b[4*t+0], off);
    float y1 = __fadd_rn(g_top_b[4*t+1], off);
    float x2 = __fadd_rn(g_top_b[4*t+2], off);
    float y2 = __fadd_rn(g_top_b[4*t+3], off);
    g_ob[4*t+0]=x1; g_ob[4*t+1]=y1; g_ob[4*t+2]=x2; g_ob[4*t+3]=y2;
    g_area[t] = __fmul_rn(__fadd_rn(__fsub_rn(x2,x1),1.0f),
                          __fadd_rn(__fsub_rn(y2,y1),1.0f));
}

// ---- 8. IoU > 0.6 suppression bitmask (rows padded to 1024) ----
__global__ __launch_bounds__(64) void k_mask(){
    int b  = blockIdx.z;
    int i  = blockIdx.x*64 + threadIdx.x;
    int j0 = blockIdx.y*64;
    __shared__ float sx1[64],sy1[64],sx2[64],sy2[64],sa[64];
    int jj = j0 + threadIdx.x;
    if (jj < MAXD){
        int tj = b*MAXD + jj;
        sx1[threadIdx.x]=g_ob[4*tj];   sy1[threadIdx.x]=g_ob[4*tj+1];
        sx2[threadIdx.x]=g_ob[4*tj+2]; sy2[threadIdx.x]=g_ob[4*tj+3];
        sa[threadIdx.x]=g_area[tj];
    }
    __syncthreads();
    if (i >= MAXD) return;
    int ti = b*MAXD + i;
    float x1=g_ob[4*ti], y1=g_ob[4*ti+1], x2=g_ob[4*ti+2], y2=g_ob[4*ti+3], ai=g_area[ti];
    unsigned long long word = 0;
    int jn = min(64, MAXD - j0);
    for (int k=0;k<jn;k++){
        float xx1=fmaxf(x1,sx1[k]), yy1=fmaxf(y1,sy1[k]);
        float xx2=fminf(x2,sx2[k]), yy2=fminf(y2,sy2[k]);
        float iw=fmaxf(__fadd_rn(__fsub_rn(xx2,xx1),1.0f),0.0f);
        float ih=fmaxf(__fadd_rn(__fsub_rn(yy2,yy1),1.0f),0.0f);
        float inter=__fmul_rn(iw,ih);
        float iou=__fdiv_rn(inter, __fsub_rn(__fadd_rn(ai,sa[k]),inter));
        if (iou > 0.6f) word |= (1ull<<k);
    }
    g_mask[((size_t)b*NPAD + i)*MASKW + blockIdx.y] = word;
}

// ---- 9. greedy scan: whole mask in smem, chunked (1 shfl per 64 items) ----
__global__ void k_scan(){
    extern __shared__ unsigned long long sm[];                  // NPAD*16 words
    unsigned char* sv = (unsigned char*)(sm + NPAD*MASKW);      // NPAD valid bytes
    int b = blockIdx.x, tid = threadIdx.x;
    const unsigned long long* src = &g_mask[(size_t)b*NPAD*MASKW];
    for (int i = tid; i < NPAD*MASKW; i += blockDim.x)
        sm[i] = (i < MAXD*MASKW) ? src[i] : 0ull;
    for (int j = tid; j < NPAD; j += blockDim.x)
        sv[j] = (j < MAXD) ? g_valid[b*MAXD + j] : 0;
    __syncthreads();
    if (tid < 32){
        int lane = tid;
        unsigned long long removed = 0, keepw = 0;
        for (int c = 0; c < MASKW; c++){
            unsigned long long rw = __shfl_sync(0xffffffffu, removed, c);
            unsigned long long sup = rw, kd = 0;
            #pragma unroll 8
            for (int i = 0; i < 64; i++){
                unsigned long long d = sm[(c*64 + i)*MASKW + c]; // diagonal block
                bool k = sv[c*64 + i] && !((sup >> i) & 1ull);
                if (k){ kd |= 1ull << i; sup |= d; }
            }
            if (lane == c) keepw = kd;
            if (lane < MASKW){
                unsigned long long t = kd;
                while (t){
                    int i = __ffsll((long long)t) - 1;
                    t &= t - 1;
                    removed |= sm[(size_t)(c*64 + i)*MASKW + lane];
                }
            }
        }
        if (lane < MASKW) g_keepw[b*MASKW + lane] = keepw;
    }
}

// ---- 10. clip + mask + write outputs ----
__global__ void k_out(float* __restrict__ out){
    int t = blockIdx.x*blockDim.x + threadIdx.x;
    if (t >= TOPN) return;
    int b = t / MAXD, j = t - b*MAXD;
    int keep = (int)((g_keepw[b*MASKW + (j >> 6)] >> (j & 63)) & 1ull);
    float kf = keep ? 1.0f : 0.0f;
    out[t]        = __fmul_rn(g_top_s[t], kf);
    out[TOPN + t] = keep ? (float)g_top_c[t] : 0.0f;
    float x1 = fminf(fmaxf(g_top_b[4*t+0],0.0f),1279.0f);
    float y1 = fminf(fmaxf(g_top_b[4*t+1],0.0f),1023.0f);
    float x2 = fminf(fmaxf(g_top_b[4*t+2],0.0f),1279.0f);
    float y2 = fminf(fmaxf(g_top_b[4*t+3],0.0f),1023.0f);
    out[2*TOPN + 4*t+0]=__fmul_rn(x1,kf);
    out[2*TOPN + 4*t+1]=__fmul_rn(y1,kf);
    out[2*TOPN + 4*t+2]=__fmul_rn(x2,kf);
    out[2*TOPN + 4*t+3]=__fmul_rn(y2,kf);
    out[6*TOPN + t]=kf;
}

extern "C" void kernel_launch(void* const* d_in, const int* in_sizes, int n_in,
                              void* d_out, int out_size){
    Ptrs P;
    for (int i=0;i<30;i++) P.p[i] = (const float*)d_in[i];

    void *histp=nullptr, *ccntp=nullptr;
    cudaGetSymbolAddress(&histp, g_hist);
    cudaGetSymbolAddress(&ccntp, g_ccount);
    cudaMemsetAsync(histp, 0, sizeof(int)*NB*HBINS);
    cudaMemsetAsync(ccntp, 0, sizeof(int)*NB);

    const int scan_smem = NPAD*MASKW*8 + NPAD;   // 132096 bytes
    cudaFuncSetAttribute(k_scan, cudaFuncAttributeMaxDynamicSharedMemorySize, scan_smem);

    k_decode<<<dim3((NPB + 2047)/2048, NB), 256>>>(P);
    k_thresh<<<NB, 256>>>();
    k_compact<<<dim3((NPB + 255)/256, NB), 256>>>();
    k_rank<<<dim3(CAP/256, NB), 256>>>();
    k_gather<<<(TOPN + 255)/256, 256>>>(P);
    k_maxc<<<NB, 256>>>();
    k_offset<<<(TOPN + 127)/128, 128>>>();
    k_mask<<<dim3((MAXD + 63)/64, MASKW, NB), 64>>>();
    k_scan<<<NB, 256, scan_smem>>>();
    k_out<<<(TOPN + 255)/256, 256>>>((float*)d_out);
}

// round 4
// speedup vs baseline: 3.5410x; 1.5581x over previous
#include <cuda_runtime.h>

#define NB     16
#define NCLS   20
#define NPM    27280          // anchors per modality
#define NPB    (2*NPM)        // 54560 anchors per batch
#define TOTAL  (NB*NPB)       // 872960
#define MAXD   1000
#define NPAD   1024           // padded detections (16 x 64)
#define MASKW  16             // 1024 bits -> 16 u64 words
#define TOPN   (NB*MAXD)      // 16000
#define HBINS  8192
#define CAP    6144           // candidate capacity per batch

typedef unsigned long long u64;

struct Ptrs { const float* p[30]; };

// ---- static device scratch (no allocations allowed; statics zero-init) ----
__device__ unsigned int g_scores[TOTAL];
__device__ int          g_hist[NB*HBINS];     // zeroed by k_compact each run
__device__ int          g_thr[NB];
__device__ int          g_ccount[NB];         // zeroed by k_gather each run
__device__ u64          g_cand[NB*CAP];
__device__ u64          g_topkeys[TOPN];
__device__ float        g_top_s[TOPN];
__device__ int          g_top_c[TOPN];
__device__ float        g_top_b[TOPN*4];
__device__ unsigned char g_valid[TOPN];
__device__ float        g_ob[TOPN*4];
__device__ float        g_area[TOPN];
__device__ u64          g_mask[(size_t)NB*NPAD*MASKW];

// sigmoid exactly as passing rounds (rel_err 1.3e-8) — do not change
__device__ __forceinline__ float sigm(float x){
    return __fdiv_rn(1.0f, __fadd_rn(1.0f, expf(-x)));
}

__device__ __forceinline__ void locate(int m, int& lvl, int& pos, int& w, int& st, int& hw){
    if (m < 20480)      { lvl=0; pos=m;        w=160; st=8;   hw=20480; }
    else if (m < 25600) { lvl=1; pos=m-20480;  w=80;  st=16;  hw=5120;  }
    else if (m < 26880) { lvl=2; pos=m-25600;  w=40;  st=32;  hw=1280;  }
    else if (m < 27200) { lvl=3; pos=m-26880;  w=20;  st=64;  hw=320;   }
    else                { lvl=4; pos=m-27200;  w=10;  st=128; hw=80;    }
}

// ---- 1. decode scores + per-batch smem histogram ----
__global__ __launch_bounds__(256) void k_decode(Ptrs P){
    __shared__ int sh[HBINS];
    int b = blockIdx.y;
    for (int i = threadIdx.x; i < HBINS; i += 256) sh[i] = 0;
    __syncthreads();
    int base = blockIdx.x * 2048;
    #pragma unroll
    for (int r = 0; r < 8; r++){
        int n = base + r*256 + threadIdx.x;
        if (n < NPB){
            int mod = (n >= NPM) ? 1 : 0;
            int m   = n - mod*NPM;
            int lvl,pos,w,st,hw; locate(m,lvl,pos,w,st,hw);
            const float* __restrict__ cls = P.p[mod*15 + lvl];
            const float* __restrict__ cnt = P.p[mod*15 + 5 + lvl];
            int cbase = b*NCLS*hw + pos;
            float lm = cls[cbase];
            #pragma unroll
            for (int c=1;c<NCLS;c++) lm = fmaxf(lm, cls[cbase + c*hw]);
            float pmax = sigm(lm);                 // max_c sigm == sigm(max_c)
            float q = sigm(cnt[b*hw + pos]);
            float score = __fsqrt_rn(__fmul_rn(pmax, q));
            unsigned int sb = __float_as_uint(score);
            g_scores[b*NPB + n] = sb;
            atomicAdd(&sh[sb >> 17], 1);
        }
    }
    __syncthreads();
    for (int i = threadIdx.x; i < HBINS; i += 256){
        int v = sh[i];
        if (v) atomicAdd(&g_hist[b*HBINS + i], v);
    }
}

// ---- 2. per-batch bin threshold ----
__global__ void k_thresh(){
    int b = blockIdx.x;
    __shared__ int gsum[256];
    const int* h = &g_hist[b*HBINS];
    int s = 0;
    #pragma unroll 8
    for (int k = 0; k < 32; k++) s += h[threadIdx.x*32 + k];
    gsum[threadIdx.x] = s;
    __syncthreads();
    if (threadIdx.x == 0){
        int acc = 0, g = 255;
        while (g > 0 && acc + gsum[g] < MAXD){ acc += gsum[g]; g--; }
        int T = g*32;
        for (int k = 31; k >= 0; k--){
            acc += h[g*32 + k];
            if (acc >= MAXD){ T = g*32 + k; break; }
        }
        g_thr[b] = T;
    }
}

// ---- 3. compact candidates; also re-zero g_hist for next run ----
__global__ void k_compact(){
    int lid = (blockIdx.y*gridDim.x + blockIdx.x)*256 + threadIdx.x;
    if (lid < NB*HBINS) g_hist[lid] = 0;
    int n = blockIdx.x*256 + threadIdx.x;
    if (n >= NPB) return;
    int b = blockIdx.y;
    unsigned int sb = g_scores[b*NPB + n];
    if ((int)(sb >> 17) >= g_thr[b]){
        int slot = atomicAdd(&g_ccount[b], 1);
        if (slot < CAP)
            g_cand[b*CAP + slot] =
                ((u64)sb << 28) | (u64)(0x0FFFFFFFu - (unsigned)n);
    }
}

// ---- 4. rank by enumeration, early-exiting dead blocks ----
__global__ __launch_bounds__(256) void k_rank(){
    int b = blockIdx.y;
    int C = min(g_ccount[b], CAP);
    if (blockIdx.x*256 >= C) return;          // dead block: nothing to rank
    int idx = blockIdx.x*256 + threadIdx.x;
    u64 my = (idx < C) ? g_cand[b*CAP + idx] : 0ull;
    int rank = 0;
    __shared__ u64 tile[256];
    for (int t0 = 0; t0 < C; t0 += 256){
        int j = t0 + threadIdx.x;
        tile[threadIdx.x] = (j < C) ? g_cand[b*CAP + j] : 0ull;
        __syncthreads();
        int tn = min(256, C - t0);
        #pragma unroll 8
        for (int k = 0; k < tn; k++) rank += (tile[k] > my) ? 1 : 0;
        __syncthreads();
    }
    if (idx < C && rank < MAXD) g_topkeys[b*MAXD + rank] = my;
}

// ---- 5. gather class/box for selected anchors; re-zero g_ccount ----
__global__ void k_gather(Ptrs P){
    if (blockIdx.x == 0 && threadIdx.x < NB) g_ccount[threadIdx.x] = 0;
    int t = blockIdx.x*blockDim.x + threadIdx.x;
    if (t >= TOPN) return;
    int b = t / MAXD;
    u64 key = g_topkeys[t];
    float score = __uint_as_float((unsigned int)(key >> 28));
    int n = 0x0FFFFFFF - (int)(key & 0x0FFFFFFFull);
    int mod = (n >= NPM) ? 1 : 0;
    int m = n - mod*NPM;
    int lvl,pos,w,st,hw; locate(m,lvl,pos,w,st,hw);
    const float* cls = P.p[mod*15 + lvl];
    const float* reg = P.p[mod*15 + 10 + lvl];
    int cbase = b*NCLS*hw + pos;
    float best = sigm(cls[cbase]); int bi = 0;   // argmax in sigmoid space (exact ties)
    #pragma unroll
    for (int c=1;c<NCLS;c++){ float s = sigm(cls[cbase + c*hw]); if (s > best){best=s;bi=c;} }
    int y = pos / w, x = pos - y*w;
    float fx = (float)(x*st + (st>>1));
    float fy = (float)(y*st + (st>>1));
    int rbase = b*4*hw + pos;
    float r0=reg[rbase], r1=reg[rbase+hw], r2=reg[rbase+2*hw], r3=reg[rbase+3*hw];
    g_top_s[t] = score;
    g_top_c[t] = bi + 1;
    g_top_b[4*t+0] = __fsub_rn(fx, r0);
    g_top_b[4*t+1] = __fsub_rn(fy, r1);
    g_top_b[4*t+2] = __fadd_rn(fx, r2);
    g_top_b[4*t+3] = __fadd_rn(fy, r3);
    g_valid[t] = (score >= 0.05f) ? 1 : 0;
}

// ---- 6. fused: per-batch maxc reduction + class-offset boxes + areas ----
__global__ __launch_bounds__(256) void k_maxoff(){
    int b = blockIdx.x;
    __shared__ float red[256];
    __shared__ float s_maxc;
    float mx = -INFINITY;
    for (int j = threadIdx.x; j < MAXD; j += 256){
        int t = b*MAXD + j;
        if (g_valid[t]){
            const float* bx = &g_top_b[4*t];
            mx = fmaxf(mx, fmaxf(fmaxf(bx[0],bx[1]), fmaxf(bx[2],bx[3])));
        } else {
            mx = fmaxf(mx, 0.0f);
        }
    }
    red[threadIdx.x] = mx; __syncthreads();
    for (int s=128; s>0; s>>=1){
        if (threadIdx.x < s) red[threadIdx.x] = fmaxf(red[threadIdx.x], red[threadIdx.x+s]);
        __syncthreads();
    }
    if (threadIdx.x==0) s_maxc = red[0];
    __syncthreads();
    float mc1 = __fadd_rn(s_maxc, 1.0f);
    for (int j = threadIdx.x; j < MAXD; j += 256){
        int t = b*MAXD + j;
        float off = __fmul_rn((float)g_top_c[t], mc1);
        float x1 = __fadd_rn(g_top_b[4*t+0], off);
        float y1 = __fadd_rn(g_top_b[4*t+1], off);
        float x2 = __fadd_rn(g_top_b[4*t+2], off);
        float y2 = __fadd_rn(g_top_b[4*t+3], off);
        g_ob[4*t+0]=x1; g_ob[4*t+1]=y1; g_ob[4*t+2]=x2; g_ob[4*t+3]=y2;
        g_area[t] = __fmul_rn(__fadd_rn(__fsub_rn(x2,x1),1.0f),
                              __fadd_rn(__fsub_rn(y2,y1),1.0f));
    }
}

// ---- 7. IoU > 0.6 suppression bitmask ----
__global__ __launch_bounds__(64) void k_mask(){
    int b  = blockIdx.z;
    int i  = blockIdx.x*64 + threadIdx.x;
    int j0 = blockIdx.y*64;
    __shared__ float sx1[64],sy1[64],sx2[64],sy2[64],sa[64];
    int jj = j0 + threadIdx.x;
    if (jj < MAXD){
        int tj = b*MAXD + jj;
        sx1[threadIdx.x]=g_ob[4*tj];   sy1[threadIdx.x]=g_ob[4*tj+1];
        sx2[threadIdx.x]=g_ob[4*tj+2]; sy2[threadIdx.x]=g_ob[4*tj+3];
        sa[threadIdx.x]=g_area[tj];
    }
    __syncthreads();
    if (i >= MAXD) return;
    int ti = b*MAXD + i;
    float x1=g_ob[4*ti], y1=g_ob[4*ti+1], x2=g_ob[4*ti+2], y2=g_ob[4*ti+3], ai=g_area[ti];
    u64 word = 0;
    int jn = min(64, MAXD - j0);
    for (int k=0;k<jn;k++){
        float xx1=fmaxf(x1,sx1[k]), yy1=fmaxf(y1,sy1[k]);
        float xx2=fminf(x2,sx2[k]), yy2=fminf(y2,sy2[k]);
        float iw=fmaxf(__fadd_rn(__fsub_rn(xx2,xx1),1.0f),0.0f);
        float ih=fmaxf(__fadd_rn(__fsub_rn(yy2,yy1),1.0f),0.0f);
        float inter=__fmul_rn(iw,ih);
        float iou=__fdiv_rn(inter, __fsub_rn(__fadd_rn(ai,sa[k]),inter));
        if (iou > 0.6f) word |= (1ull<<k);
    }
    g_mask[((size_t)b*NPAD + i)*MASKW + blockIdx.y] = word;
}

// ---- 8. fused greedy scan + output write (1 block per batch) ----
// Diagonal words prefetched to REGISTERS so the serial loop is pure ALU;
// removed-word updates are independent predicated LDS (MLP-pipelined).
__global__ void k_scan_out(float* __restrict__ out){
    extern __shared__ u64 sm[];                    // NPAD*MASKW words
    __shared__ u64 svm[MASKW];                     // validity bit words
    __shared__ u64 skeep[MASKW];                   // result keep words
    int b = blockIdx.x, tid = threadIdx.x;
    const u64* src = &g_mask[(size_t)b*NPAD*MASKW];
    for (int i = tid; i < NPAD*MASKW; i += blockDim.x)
        sm[i] = (i < MAXD*MASKW) ? src[i] : 0ull;
    if (tid < MASKW){
        u64 w = 0;
        for (int i = 0; i < 64; i++){
            int j = tid*64 + i;
            if (j < MAXD && g_valid[b*MAXD + j]) w |= 1ull << i;
        }
        svm[tid] = w;
    }
    __syncthreads();
    if (tid < 32){
        int lane = tid;
        u64 removed = 0;
        for (int c = 0; c < MASKW; c++){
            // prefetch diagonal block to registers (broadcast LDS, independent)
            u64 dreg[64];
            #pragma unroll
            for (int i = 0; i < 64; i++) dreg[i] = sm[(c*64 + i)*MASKW + c];
            u64 sup = __shfl_sync(0xffffffffu, removed, c);
            u64 vmc = svm[c];
            u64 kd = 0;
            #pragma unroll
            for (int i = 0; i < 64; i++){          // pure-ALU serial chain
                bool k = ((vmc >> i) & 1ull) && !((sup >> i) & 1ull);
                if (k){ kd |= 1ull << i; sup |= dreg[i]; }
            }
            if (lane == c) skeep[c] = kd;
            if (lane < MASKW){
                #pragma unroll
                for (int i = 0; i < 64; i++)       // independent predicated loads
                    if ((kd >> i) & 1ull)
                        removed |= sm[(size_t)(c*64 + i)*MASKW + lane];
            }
        }
    }
    __syncthreads();
    for (int j = tid; j < MAXD; j += blockDim.x){
        int t = b*MAXD + j;
        int keep = (int)((skeep[j >> 6] >> (j & 63)) & 1ull);
        float kf = keep ? 1.0f : 0.0f;
        out[t]        = __fmul_rn(g_top_s[t], kf);
        out[TOPN + t] = keep ? (float)g_top_c[t] : 0.0f;
        float x1 = fminf(fmaxf(g_top_b[4*t+0],0.0f),1279.0f);
        float y1 = fminf(fmaxf(g_top_b[4*t+1],0.0f),1023.0f);
        float x2 = fminf(fmaxf(g_top_b[4*t+2],0.0f),1279.0f);
        float y2 = fminf(fmaxf(g_top_b[4*t+3],0.0f),1023.0f);
        out[2*TOPN + 4*t+0]=__fmul_rn(x1,kf);
        out[2*TOPN + 4*t+1]=__fmul_rn(y1,kf);
        out[2*TOPN + 4*t+2]=__fmul_rn(x2,kf);
        out[2*TOPN + 4*t+3]=__fmul_rn(y2,kf);
        out[6*TOPN + t]=kf;
    }
}

extern "C" void kernel_launch(void* const* d_in, const int* in_sizes, int n_in,
                              void* d_out, int out_size){
    Ptrs P;
    for (int i=0;i<30;i++) P.p[i] = (const float*)d_in[i];

    const int scan_smem = NPAD*MASKW*8;   // 131072 bytes
    cudaFuncSetAttribute(k_scan_out, cudaFuncAttributeMaxDynamicSharedMemorySize, scan_smem);

    k_decode <<<dim3((NPB + 2047)/2048, NB), 256>>>(P);
    k_thresh <<<NB, 256>>>();
    k_compact<<<dim3((NPB + 255)/256, NB), 256>>>();
    k_rank   <<<dim3(CAP/256, NB), 256>>>();
    k_gather <<<(TOPN + 255)/256, 256>>>(P);
    k_maxoff <<<NB, 256>>>();
    k_mask   <<<dim3((MAXD + 63)/64, MASKW, NB), 64>>>();
    k_scan_out<<<NB, 256, scan_smem>>>((float*)d_out);
}